// round 9
// baseline (speedup 1.0000x reference)
#include <cuda_runtime.h>
#include <cuda_fp16.h>
#include <stdint.h>
#include <float.h>

// ---------------- Problem constants ----------------
#define BATCH   4
#define DDIM    512
#define TQ      4096
#define MROWS   (BATCH * TQ)      // 16384
#define NCODES  8192
#define NGRP    (NCODES / 16)     // 512 16-code groups per row

// ---------------- GEMM tiling (int8) ----------------
#define BM 128
#define BN 128
#define BK 64                     // int8 elems per stage = 64 bytes/row
#define NBLK   (NCODES / BN)      // 64
#define NSTAGE (DDIM / BK)        // 8

#define ROWPITCH 80               // 64B data + 16B pad: ldsm conflict-free
#define AMAT  (128 * ROWPITCH)    // 10240
#define B_OFF AMAT
#define STAGE (2 * AMAT)          // 20480
#define SMEM_GEMM (2 * STAGE)     // 40960 (static)

// ---------------- Device scratch ----------------
__device__ float g_zt[(size_t)MROWS * DDIM];          // transposed z (fp32), 64MB
__device__ unsigned g_zq[(size_t)MROWS * DDIM / 4];   // int8 quantized z, 8MB
__device__ unsigned g_eq[(size_t)NCODES * DDIM / 4];  // int8 quantized e', 4MB
__device__ float g_sz[MROWS], g_P[MROWS];             // z scales + bound terms
__device__ float g_se[NCODES], g_Q[NCODES];           // e scales + bound terms
__device__ float g_inv_norm[NCODES];
__device__ __half g_gmax[(size_t)MROWS * NGRP];       // per-16-group max upper bound, 16MB
__device__ unsigned g_maxlo[MROWS];                   // fkey(max lower bound)
__device__ unsigned long long g_best[MROWS];

// ---------------- helpers ----------------
__device__ __forceinline__ uint32_t smem_u32(const void* p) {
    uint32_t a;
    asm("{ .reg .u64 t; cvta.to.shared.u64 t, %1; cvt.u32.u64 %0, t; }" : "=r"(a) : "l"(p));
    return a;
}
__device__ __forceinline__ void cpasync16(uint32_t dst, const void* src) {
    asm volatile("cp.async.cg.shared.global [%0], [%1], 16;" :: "r"(dst), "l"(src) : "memory");
}
#define CP_COMMIT() asm volatile("cp.async.commit_group;" ::: "memory")
#define CP_WAIT(n)  asm volatile("cp.async.wait_group %0;" :: "n"(n) : "memory")

#define LDSM4(R, addr) \
    asm volatile("ldmatrix.sync.aligned.m8n8.x4.shared.b16 {%0,%1,%2,%3}, [%4];" \
                 : "=r"((R)[0]), "=r"((R)[1]), "=r"((R)[2]), "=r"((R)[3]) : "r"(addr))

#define MMA_S8(C, A, b0v, b1v) \
    asm volatile("mma.sync.aligned.m16n8k32.row.col.s32.s8.s8.s32 " \
                 "{%0,%1,%2,%3}, {%4,%5,%6,%7}, {%8,%9}, {%0,%1,%2,%3};" \
                 : "+r"((C)[0]), "+r"((C)[1]), "+r"((C)[2]), "+r"((C)[3]) \
                 : "r"((A)[0]), "r"((A)[1]), "r"((A)[2]), "r"((A)[3]), "r"(b0v), "r"(b1v))

__device__ __forceinline__ unsigned int fkey(float v) {
    unsigned int u = __float_as_uint(v);
    return (u & 0x80000000u) ? ~u : (u | 0x80000000u);
}
__device__ __forceinline__ float unkey(unsigned int k) {
    unsigned int u = (k & 0x80000000u) ? (k ^ 0x80000000u) : ~k;
    return __uint_as_float(u);
}
__device__ __forceinline__ unsigned long long pack_key(float v, int n) {
    return ((unsigned long long)fkey(v) << 32) | (unsigned long long)(0xFFFFFFFFu - (unsigned)n);
}

// ---------------- Small kernels ----------------
__global__ void init_maxlo_kernel() {
    int i = blockIdx.x * blockDim.x + threadIdx.x;
    if (i < MROWS) g_maxlo[i] = 0u;
}

__global__ void inv_norm_kernel(const float* __restrict__ emb) {
    int warp = (blockIdx.x * blockDim.x + threadIdx.x) >> 5;
    int lane = threadIdx.x & 31;
    if (warp >= NCODES) return;
    const float* row = emb + (size_t)warp * DDIM;
    float s = 0.f;
    #pragma unroll
    for (int k = lane; k < DDIM; k += 32) { float v = row[k]; s = fmaf(v, v, s); }
    #pragma unroll
    for (int o = 16; o; o >>= 1) s += __shfl_down_sync(0xffffffffu, s, o);
    if (lane == 0) g_inv_norm[warp] = 1.0f / fmaxf(sqrtf(s), 1e-12f);
}

// Transpose z: [b][k][t] -> z_t[m=b*TQ+t][k] fp32
__global__ __launch_bounds__(256) void transpose_z_kernel(const float* __restrict__ z) {
    __shared__ float tile[32][33];
    int b  = blockIdx.z;
    int k0 = blockIdx.y * 32;
    int t0 = blockIdx.x * 32;
    int tx = threadIdx.x & 31, ty = threadIdx.x >> 5;
    #pragma unroll
    for (int i = 0; i < 4; i++) {
        int kl = ty + i * 8;
        tile[kl][tx] = z[((size_t)b * DDIM + k0 + kl) * TQ + t0 + tx];
    }
    __syncthreads();
    #pragma unroll
    for (int i = 0; i < 4; i++) {
        int tl = ty + i * 8;
        int m = b * TQ + t0 + tl;
        g_zt[(size_t)m * DDIM + k0 + tx] = tile[tx][tl];
    }
}

// Generic per-row int8 quantizer: warp per row of 512 floats.
template <int ADDC>
__global__ __launch_bounds__(256) void quant_kernel(const float* __restrict__ src,
                                                    unsigned* __restrict__ qdst,
                                                    float* __restrict__ scale,
                                                    float* __restrict__ bterm,
                                                    const float* __restrict__ rowscale) {
    int row = blockIdx.x * 8 + (threadIdx.x >> 5);
    int lane = threadIdx.x & 31;
    float rs = rowscale ? rowscale[row] : 1.0f;
    float v[16];
    const float4* sp = (const float4*)(src + (size_t)row * DDIM + lane * 16);
    #pragma unroll
    for (int j = 0; j < 4; j++) {
        float4 f = sp[j];
        v[j*4+0] = f.x * rs; v[j*4+1] = f.y * rs; v[j*4+2] = f.z * rs; v[j*4+3] = f.w * rs;
    }
    float amax = 0.f;
    #pragma unroll
    for (int j = 0; j < 16; j++) amax = fmaxf(amax, fabsf(v[j]));
    #pragma unroll
    for (int o = 16; o; o >>= 1) amax = fmaxf(amax, __shfl_xor_sync(0xffffffffu, amax, o));
    amax = fmaxf(amax, 1e-30f);
    float sc = amax / 127.0f;
    float inv = 127.0f / amax;
    int q[16], sabs = 0;
    #pragma unroll
    for (int j = 0; j < 16; j++) {
        int qq = __float2int_rn(v[j] * inv);
        qq = max(-127, min(127, qq));
        q[j] = qq;
        sabs += abs(qq);
    }
    #pragma unroll
    for (int o = 16; o; o >>= 1) sabs += __shfl_xor_sync(0xffffffffu, sabs, o);
    unsigned w[4];
    #pragma unroll
    for (int g = 0; g < 4; g++)
        w[g] = (unsigned)(q[g*4] & 0xFF) | ((unsigned)(q[g*4+1] & 0xFF) << 8) |
               ((unsigned)(q[g*4+2] & 0xFF) << 16) | ((unsigned)(q[g*4+3] & 0xFF) << 24);
    uint4* dp = (uint4*)(qdst + (size_t)row * (DDIM / 4) + lane * 4);
    *dp = make_uint4(w[0], w[1], w[2], w[3]);
    if (lane == 0) {
        scale[row] = sc;
        bterm[row] = 0.5f * (float)sabs + (float)ADDC;
    }
}

// ---------------- int8 GEMM + group-max bound epilogue ----------------
__device__ __forceinline__ void load_stage(uint32_t sbase, int tid, int m0, int n0, int k0) {
    #pragma unroll
    for (int it = 0; it < 2; it++) {
        int c = it * 256 + tid;
        int row = c >> 2, col = c & 3;
        cpasync16(sbase + (uint32_t)(row * ROWPITCH + col * 16),
                  (const char*)g_zq + (size_t)(m0 + row) * DDIM + k0 + col * 16);
    }
    #pragma unroll
    for (int it = 0; it < 2; it++) {
        int c = it * 256 + tid;
        int row = c >> 2, col = c & 3;
        cpasync16(sbase + B_OFF + (uint32_t)(row * ROWPITCH + col * 16),
                  (const char*)g_eq + (size_t)(n0 + row) * DDIM + k0 + col * 16);
    }
}

__global__ __launch_bounds__(256, 2)
void gemm_bound_kernel() {
    __shared__ char smem[SMEM_GEMM];
    __shared__ float s_sz[128], s_P[128], s_se[128], s_Q[128];
    __shared__ unsigned s_lo[128];
    uint32_t sb = smem_u32(smem);
    const int tid = threadIdx.x;
    const int w = tid >> 5, l = tid & 31;
    const int wy = w >> 2, wx = w & 3;
    const int m0 = blockIdx.y * BM;
    const int n0 = blockIdx.x * BN;

    if (tid < 128) {
        s_sz[tid] = g_sz[m0 + tid];
        s_P[tid]  = g_P[m0 + tid];
        s_se[tid] = g_se[n0 + tid];
        s_Q[tid]  = g_Q[n0 + tid];
        s_lo[tid] = 0u;
    }

    int c[4][4][4];
    #pragma unroll
    for (int i = 0; i < 4; i++)
        #pragma unroll
        for (int j = 0; j < 4; j++)
            #pragma unroll
            for (int r = 0; r < 4; r++) c[i][j][r] = 0;

    const uint32_t aBase = sb + (uint32_t)((wy * 64 + (l & 15)) * ROWPITCH + ((l >> 4) << 4));
    const uint32_t bBase = sb + B_OFF +
        (uint32_t)((wx * 32 + ((l >> 4) & 1) * 8 + (l & 7)) * ROWPITCH + ((l >> 3) & 1) * 16);

    load_stage(sb, tid, m0, n0, 0);
    CP_COMMIT();

    #pragma unroll 1
    for (int s = 0; s < NSTAGE; s++) {
        if (s > 0) __syncthreads();
        if (s + 1 < NSTAGE) {
            load_stage(sb + ((s + 1) & 1) * STAGE, tid, m0, n0, (s + 1) * BK);
            CP_COMMIT();
            CP_WAIT(1);
        } else {
            CP_WAIT(0);
        }
        __syncthreads();

        const uint32_t so = (uint32_t)((s & 1) * STAGE);
        #pragma unroll
        for (int ks = 0; ks < 2; ks++) {
            uint32_t ah[4][4];
            #pragma unroll
            for (int mi = 0; mi < 4; mi++)
                LDSM4(ah[mi], aBase + so + (uint32_t)(mi * 16 * ROWPITCH + ks * 32));
            uint32_t bh[2][4];
            #pragma unroll
            for (int np = 0; np < 2; np++)
                LDSM4(bh[np], bBase + so + (uint32_t)(np * 16 * ROWPITCH + ks * 32));
            #pragma unroll
            for (int mi = 0; mi < 4; mi++)
                #pragma unroll
                for (int ni = 0; ni < 4; ni++) {
                    int np = ni >> 1, q = (ni & 1) * 2;
                    MMA_S8(c[mi][ni], ah[mi], bh[np][q], bh[np][q + 1]);
                }
        }
    }

    // -------- epilogue: group maxes of upper bounds + row max lower bound --------
    #pragma unroll
    for (int mi = 0; mi < 4; mi++) {
        int rl = wy * 64 + mi * 16 + (l >> 2);
        float szl = s_sz[rl],     Pl = s_P[rl];
        float szh = s_sz[rl + 8], Ph = s_P[rl + 8];
        float lomax_l = -FLT_MAX, lomax_h = -FLT_MAX;
        float g0l = -FLT_MAX, g1l = -FLT_MAX, g0h = -FLT_MAX, g1h = -FLT_MAX;
        #pragma unroll
        for (int ni = 0; ni < 4; ni++) {
            int ncol = wx * 32 + ni * 8 + 2 * (l & 3);
            float se0 = s_se[ncol], Q0 = s_Q[ncol];
            float se1 = s_se[ncol + 1], Q1 = s_Q[ncol + 1];
            float d00 = (float)c[mi][ni][0], d01 = (float)c[mi][ni][1];
            float d10 = (float)c[mi][ni][2], d11 = (float)c[mi][ni][3];
            float k00 = szl * se0, k01 = szl * se1, k10 = szh * se0, k11 = szh * se1;
            float b00 = Pl + Q0, b01 = Pl + Q1, b10 = Ph + Q0, b11 = Ph + Q1;
            float up00 = k00 * (d00 + b00), lo00 = k00 * (d00 - b00);
            float up01 = k01 * (d01 + b01), lo01 = k01 * (d01 - b01);
            float up10 = k10 * (d10 + b10), lo10 = k10 * (d10 - b10);
            float up11 = k11 * (d11 + b11), lo11 = k11 * (d11 - b11);
            lomax_l = fmaxf(lomax_l, fmaxf(lo00, lo01));
            lomax_h = fmaxf(lomax_h, fmaxf(lo10, lo11));
            float ul = fmaxf(up00, up01), uh = fmaxf(up10, up11);
            if (ni < 2) { g0l = fmaxf(g0l, ul); g0h = fmaxf(g0h, uh); }
            else        { g1l = fmaxf(g1l, ul); g1h = fmaxf(g1h, uh); }
        }
        // quad reduce group maxes (lanes sharing a row: l^1, l^2)
        #pragma unroll
        for (int o = 1; o < 4; o <<= 1) {
            g0l = fmaxf(g0l, __shfl_xor_sync(0xffffffffu, g0l, o));
            g1l = fmaxf(g1l, __shfl_xor_sync(0xffffffffu, g1l, o));
            g0h = fmaxf(g0h, __shfl_xor_sync(0xffffffffu, g0h, o));
            g1h = fmaxf(g1h, __shfl_xor_sync(0xffffffffu, g1h, o));
        }
        if ((l & 3) == 0) {
            int gidx = (n0 >> 5) + wx;   // half2 index within row (2 groups per half2)
            ((__half2*)g_gmax)[(size_t)(m0 + rl) * (NGRP / 2) + gidx] =
                __halves2half2(__float2half_ru(g0l), __float2half_ru(g1l));
            ((__half2*)g_gmax)[(size_t)(m0 + rl + 8) * (NGRP / 2) + gidx] =
                __halves2half2(__float2half_ru(g0h), __float2half_ru(g1h));
        }
        atomicMax(&s_lo[rl], fkey(lomax_l));
        atomicMax(&s_lo[rl + 8], fkey(lomax_h));
    }
    __syncthreads();
    if (tid < 128) atomicMax(&g_maxlo[m0 + tid], s_lo[tid]);
}

// ---------------- Group scan + exact fp32 rescore (warp per row) ----------------
__global__ __launch_bounds__(256)
void scan_rescore_kernel(const float* __restrict__ emb) {
    int m = blockIdx.x * 8 + (threadIdx.x >> 5);
    int lane = threadIdx.x & 31;
    const unsigned FULL = 0xffffffffu;

    float zr[16];
    const float* zrow = g_zt + (size_t)m * DDIM;
    #pragma unroll
    for (int i = 0; i < 16; i++) zr[i] = zrow[lane + 32 * i];

    float maxlo = unkey(g_maxlo[m]);
    unsigned long long best = 0ULL;

    // group-max row: 512 halves = 256 half2; lane reads 8 (stride 32) -> 16 flag bits
    const __half2* gmrow = (const __half2*)(g_gmax + (size_t)m * NGRP);
    unsigned mask = 0;
    #pragma unroll
    for (int i = 0; i < 8; i++) {
        float2 f = __half22float2(gmrow[lane + 32 * i]);
        if (f.x >= maxlo) mask |= 1u << (2 * i);
        if (f.y >= maxlo) mask |= 1u << (2 * i + 1);
    }

    unsigned act = __ballot_sync(FULL, mask != 0);
    while (act) {
        int src = __ffs(act) - 1;
        act &= act - 1;
        unsigned mm = __shfl_sync(FULL, mask, src);
        while (mm) {
            int bit = __ffs(mm) - 1;
            mm &= mm - 1;
            int h2 = src + 32 * (bit >> 1);
            int g = 2 * h2 + (bit & 1);
            // rescore all 16 codes of the flagged group exactly (warp per code)
            #pragma unroll 1
            for (int j = 0; j < 16; j++) {
                int n = g * 16 + j;
                const float* er = emb + (size_t)n * DDIM;
                float s = 0.f;
                #pragma unroll
                for (int i = 0; i < 16; i++) s = fmaf(zr[i], er[lane + 32 * i], s);
                #pragma unroll
                for (int o = 16; o; o >>= 1) s += __shfl_xor_sync(FULL, s, o);
                s *= g_inv_norm[n];
                unsigned long long key = pack_key(s, n);
                if (key > best) best = key;
            }
        }
    }
    if (lane == 0) g_best[m] = best;
}

// ---------------- Gather + outputs ----------------
__global__ __launch_bounds__(256)
void gather_kernel(const float* __restrict__ z, const float* __restrict__ emb,
                   float* __restrict__ out) {
    __shared__ float tile[32][33];
    __shared__ int sidx[32];

    const int r0 = blockIdx.x * 32;
    const int tid = threadIdx.x;
    const int tx = tid & 31;
    const int tyw = tid >> 5;

    if (tid < 32) {
        unsigned long long p = g_best[r0 + tid];
        int n = (int)(0xFFFFFFFFu - (unsigned)(p & 0xFFFFFFFFu));
        sidx[tid] = n;
        out[(size_t)BATCH * DDIM * TQ + r0 + tid] = (float)n;
    }
    __syncthreads();

    const int b = r0 / TQ;
    const int t0 = r0 % TQ;
    float* out_st = out;
    float* out_q  = out + (size_t)BATCH * DDIM * TQ + MROWS;

    for (int cc = 0; cc < DDIM; cc += 32) {
        #pragma unroll
        for (int i = 0; i < 4; i++) {
            int row = tyw + i * 8;
            tile[row][tx] = emb[(size_t)sidx[row] * DDIM + cc + tx];
        }
        __syncthreads();
        #pragma unroll
        for (int i = 0; i < 4; i++) {
            int cidx = cc + tyw + i * 8;
            size_t o = ((size_t)b * DDIM + cidx) * TQ + t0 + tx;
            float v = tile[tx][tyw + i * 8];
            out_q[o] = v;
            float zz = z[o];
            out_st[o] = zz + (v - zz);
        }
        __syncthreads();
    }
}

// ---------------- Launch ----------------
extern "C" void kernel_launch(void* const* d_in, const int* in_sizes, int n_in,
                              void* d_out, int out_size) {
    const float* z   = (const float*)d_in[0];   // [4, 512, 4096]
    const float* emb = (const float*)d_in[1];   // [8192, 512]
    float* out = (float*)d_out;

    float* d_zt;
    cudaGetSymbolAddress((void**)&d_zt, g_zt);
    unsigned *d_zq, *d_eq;
    cudaGetSymbolAddress((void**)&d_zq, g_zq);
    cudaGetSymbolAddress((void**)&d_eq, g_eq);
    float *d_sz, *d_P, *d_se, *d_Q, *d_inv;
    cudaGetSymbolAddress((void**)&d_sz, g_sz);
    cudaGetSymbolAddress((void**)&d_P, g_P);
    cudaGetSymbolAddress((void**)&d_se, g_se);
    cudaGetSymbolAddress((void**)&d_Q, g_Q);
    cudaGetSymbolAddress((void**)&d_inv, g_inv_norm);

    init_maxlo_kernel<<<MROWS / 256, 256>>>();
    inv_norm_kernel<<<NCODES / 8, 256>>>(emb);
    quant_kernel<128><<<NCODES / 8, 256>>>(emb, d_eq, d_se, d_Q, d_inv);
    transpose_z_kernel<<<dim3(TQ / 32, DDIM / 32, BATCH), 256>>>(z);
    quant_kernel<128><<<MROWS / 8, 256>>>(d_zt, d_zq, d_sz, d_P, nullptr);

    gemm_bound_kernel<<<dim3(NBLK, MROWS / BM), 256>>>();

    scan_rescore_kernel<<<MROWS / 8, 256>>>(emb);
    gather_kernel<<<MROWS / 32, 256>>>(z, emb, out);
}

// round 10
// speedup vs baseline: 4.4336x; 4.4336x over previous
#include <cuda_runtime.h>
#include <cuda_fp16.h>
#include <stdint.h>
#include <float.h>

// ---------------- Problem constants ----------------
#define BATCH   4
#define DDIM    512
#define TQ      4096
#define MROWS   (BATCH * TQ)      // 16384
#define NCODES  8192

// ---------------- GEMM tiling (int8) ----------------
#define BM 128
#define BN 128
#define BK 64                     // int8 elems per stage = 64 bytes/row
#define NBLK   (NCODES / BN)      // 64
#define MBLK   (MROWS / BM)       // 128
#define NSTAGE (DDIM / BK)        // 8

#define ROWPITCH 80               // 64B data + 16B pad: uniform 16B-chunk bank spread
#define AMAT  (128 * ROWPITCH)    // 10240
#define B_OFF AMAT
#define STAGE (2 * AMAT)          // 20480
#define SMEM_GEMM (2 * STAGE)     // 40960 (static)

// ---------------- Device scratch ----------------
__device__ float g_zt[(size_t)MROWS * DDIM];          // transposed z (fp32), 64MB
__device__ unsigned g_zq[(size_t)MROWS * DDIM / 4];   // int8 quantized z, 8MB
__device__ unsigned g_eq[(size_t)NCODES * DDIM / 4];  // int8 quantized e', 4MB
__device__ float g_sz[MROWS], g_P[MROWS];             // z scales + bound terms
__device__ float g_se[NCODES], g_Q[NCODES];           // e scales + bound terms
__device__ float g_inv_norm[NCODES];
__device__ __half g_up[(size_t)MROWS * NCODES];       // upper bounds, 256MB
__device__ unsigned g_maxlo[MROWS];                   // fkey(max lower bound)
__device__ unsigned long long g_best[MROWS];

// ---------------- helpers ----------------
__device__ __forceinline__ uint32_t smem_u32(const void* p) {
    uint32_t a;
    asm("{ .reg .u64 t; cvta.to.shared.u64 t, %1; cvt.u32.u64 %0, t; }" : "=r"(a) : "l"(p));
    return a;
}
__device__ __forceinline__ void cpasync16(uint32_t dst, const void* src) {
    asm volatile("cp.async.cg.shared.global [%0], [%1], 16;" :: "r"(dst), "l"(src) : "memory");
}
#define CP_COMMIT() asm volatile("cp.async.commit_group;" ::: "memory")
#define CP_WAIT(n)  asm volatile("cp.async.wait_group %0;" :: "n"(n) : "memory")

#define LDSM4(R, addr) \
    asm volatile("ldmatrix.sync.aligned.m8n8.x4.shared.b16 {%0,%1,%2,%3}, [%4];" \
                 : "=r"((R)[0]), "=r"((R)[1]), "=r"((R)[2]), "=r"((R)[3]) : "r"(addr))

#define MMA_S8(C, A, b0v, b1v) \
    asm volatile("mma.sync.aligned.m16n8k32.row.col.s32.s8.s8.s32 " \
                 "{%0,%1,%2,%3}, {%4,%5,%6,%7}, {%8,%9}, {%0,%1,%2,%3};" \
                 : "+r"((C)[0]), "+r"((C)[1]), "+r"((C)[2]), "+r"((C)[3]) \
                 : "r"((A)[0]), "r"((A)[1]), "r"((A)[2]), "r"((A)[3]), "r"(b0v), "r"(b1v))

__device__ __forceinline__ unsigned int fkey(float v) {
    unsigned int u = __float_as_uint(v);
    return (u & 0x80000000u) ? ~u : (u | 0x80000000u);
}
__device__ __forceinline__ float unkey(unsigned int k) {
    unsigned int u = (k & 0x80000000u) ? (k ^ 0x80000000u) : ~k;
    return __uint_as_float(u);
}
__device__ __forceinline__ unsigned long long pack_key(float v, int n) {
    return ((unsigned long long)fkey(v) << 32) | (unsigned long long)(0xFFFFFFFFu - (unsigned)n);
}

// ---------------- Small kernels ----------------
// inv_norm + g_maxlo init fused (1024 blocks x 256 threads; thread i<MROWS zeroes maxlo)
__global__ void inv_norm_kernel(const float* __restrict__ emb) {
    int gidx = blockIdx.x * blockDim.x + threadIdx.x;
    if (gidx < MROWS) g_maxlo[gidx] = 0u;
    int warp = gidx >> 5;
    int lane = threadIdx.x & 31;
    if (warp >= NCODES) return;
    const float* row = emb + (size_t)warp * DDIM;
    float s = 0.f;
    #pragma unroll
    for (int k = lane; k < DDIM; k += 32) { float v = row[k]; s = fmaf(v, v, s); }
    #pragma unroll
    for (int o = 16; o; o >>= 1) s += __shfl_down_sync(0xffffffffu, s, o);
    if (lane == 0) g_inv_norm[warp] = 1.0f / fmaxf(sqrtf(s), 1e-12f);
}

// Transpose z: [b][k][t] -> z_t[m=b*TQ+t][k] fp32
__global__ __launch_bounds__(256) void transpose_z_kernel(const float* __restrict__ z) {
    __shared__ float tile[32][33];
    int b  = blockIdx.z;
    int k0 = blockIdx.y * 32;
    int t0 = blockIdx.x * 32;
    int tx = threadIdx.x & 31, ty = threadIdx.x >> 5;
    #pragma unroll
    for (int i = 0; i < 4; i++) {
        int kl = ty + i * 8;
        tile[kl][tx] = z[((size_t)b * DDIM + k0 + kl) * TQ + t0 + tx];
    }
    __syncthreads();
    #pragma unroll
    for (int i = 0; i < 4; i++) {
        int tl = ty + i * 8;
        int m = b * TQ + t0 + tl;
        g_zt[(size_t)m * DDIM + k0 + tx] = tile[tx][tl];
    }
}

// Generic per-row int8 quantizer: warp per row of 512 floats.
template <int ADDC>
__global__ __launch_bounds__(256) void quant_kernel(const float* __restrict__ src,
                                                    unsigned* __restrict__ qdst,
                                                    float* __restrict__ scale,
                                                    float* __restrict__ bterm,
                                                    const float* __restrict__ rowscale) {
    int row = blockIdx.x * 8 + (threadIdx.x >> 5);
    int lane = threadIdx.x & 31;
    float rs = rowscale ? rowscale[row] : 1.0f;
    float v[16];
    const float4* sp = (const float4*)(src + (size_t)row * DDIM + lane * 16);
    #pragma unroll
    for (int j = 0; j < 4; j++) {
        float4 f = sp[j];
        v[j*4+0] = f.x * rs; v[j*4+1] = f.y * rs; v[j*4+2] = f.z * rs; v[j*4+3] = f.w * rs;
    }
    float amax = 0.f;
    #pragma unroll
    for (int j = 0; j < 16; j++) amax = fmaxf(amax, fabsf(v[j]));
    #pragma unroll
    for (int o = 16; o; o >>= 1) amax = fmaxf(amax, __shfl_xor_sync(0xffffffffu, amax, o));
    amax = fmaxf(amax, 1e-30f);
    float sc = amax / 127.0f;
    float inv = 127.0f / amax;
    int q[16], sabs = 0;
    #pragma unroll
    for (int j = 0; j < 16; j++) {
        int qq = __float2int_rn(v[j] * inv);
        qq = max(-127, min(127, qq));
        q[j] = qq;
        sabs += abs(qq);
    }
    #pragma unroll
    for (int o = 16; o; o >>= 1) sabs += __shfl_xor_sync(0xffffffffu, sabs, o);
    unsigned w[4];
    #pragma unroll
    for (int g = 0; g < 4; g++)
        w[g] = (unsigned)(q[g*4] & 0xFF) | ((unsigned)(q[g*4+1] & 0xFF) << 8) |
               ((unsigned)(q[g*4+2] & 0xFF) << 16) | ((unsigned)(q[g*4+3] & 0xFF) << 24);
    uint4* dp = (uint4*)(qdst + (size_t)row * (DDIM / 4) + lane * 4);
    *dp = make_uint4(w[0], w[1], w[2], w[3]);
    if (lane == 0) {
        scale[row] = sc;
        bterm[row] = 0.5f * (float)sabs + (float)ADDC;
    }
}

// ---------------- int8 GEMM + bound epilogue ----------------
__device__ __forceinline__ void load_stage(uint32_t sbase, int tid, int m0, int n0, int k0) {
    #pragma unroll
    for (int it = 0; it < 2; it++) {
        int c = it * 256 + tid;
        int row = c >> 2, col = c & 3;
        cpasync16(sbase + (uint32_t)(row * ROWPITCH + col * 16),
                  (const char*)g_zq + (size_t)(m0 + row) * DDIM + k0 + col * 16);
    }
    #pragma unroll
    for (int it = 0; it < 2; it++) {
        int c = it * 256 + tid;
        int row = c >> 2, col = c & 3;
        cpasync16(sbase + B_OFF + (uint32_t)(row * ROWPITCH + col * 16),
                  (const char*)g_eq + (size_t)(n0 + row) * DDIM + k0 + col * 16);
    }
}

__global__ __launch_bounds__(256, 2)
void gemm_bound_kernel() {
    __shared__ char smem[SMEM_GEMM];
    __shared__ float s_sz[128], s_P[128], s_se[128], s_Q[128];
    __shared__ unsigned s_lo[128];
    uint32_t sb = smem_u32(smem);
    const int tid = threadIdx.x;
    const int w = tid >> 5, l = tid & 31;
    const int wy = w >> 2, wx = w & 3;

    // L2-locality swizzle: bands of 16 m-blocks, n sweeps within a band.
    const int bid  = blockIdx.x;
    const int band = bid >> 10;              // / (NBLK*16)
    const int rem  = bid & 1023;
    const int m0 = ((band << 4) | (rem & 15)) * BM;
    const int n0 = (rem >> 4) * BN;

    if (tid < 128) {
        s_sz[tid] = g_sz[m0 + tid];
        s_P[tid]  = g_P[m0 + tid];
        s_se[tid] = g_se[n0 + tid];
        s_Q[tid]  = g_Q[n0 + tid];
        s_lo[tid] = 0u;
    }

    int c[4][4][4];
    #pragma unroll
    for (int i = 0; i < 4; i++)
        #pragma unroll
        for (int j = 0; j < 4; j++)
            #pragma unroll
            for (int r = 0; r < 4; r++) c[i][j][r] = 0;

    const uint32_t aBase = sb + (uint32_t)((wy * 64 + (l & 15)) * ROWPITCH + ((l >> 4) << 4));
    const uint32_t bBase = sb + B_OFF +
        (uint32_t)((wx * 32 + ((l >> 4) & 1) * 8 + (l & 7)) * ROWPITCH + ((l >> 3) & 1) * 16);

    load_stage(sb, tid, m0, n0, 0);
    CP_COMMIT();

    #pragma unroll 1
    for (int s = 0; s < NSTAGE; s++) {
        if (s > 0) __syncthreads();
        if (s + 1 < NSTAGE) {
            load_stage(sb + ((s + 1) & 1) * STAGE, tid, m0, n0, (s + 1) * BK);
            CP_COMMIT();
            CP_WAIT(1);
        } else {
            CP_WAIT(0);
        }
        __syncthreads();

        const uint32_t so = (uint32_t)((s & 1) * STAGE);
        #pragma unroll
        for (int ks = 0; ks < 2; ks++) {
            uint32_t ah[4][4];
            #pragma unroll
            for (int mi = 0; mi < 4; mi++)
                LDSM4(ah[mi], aBase + so + (uint32_t)(mi * 16 * ROWPITCH + ks * 32));
            uint32_t bh[2][4];
            #pragma unroll
            for (int np = 0; np < 2; np++)
                LDSM4(bh[np], bBase + so + (uint32_t)(np * 16 * ROWPITCH + ks * 32));
            #pragma unroll
            for (int mi = 0; mi < 4; mi++)
                #pragma unroll
                for (int ni = 0; ni < 4; ni++) {
                    int np = ni >> 1, q = (ni & 1) * 2;
                    MMA_S8(c[mi][ni], ah[mi], bh[np][q], bh[np][q + 1]);
                }
        }
    }

    // -------- epilogue: up/lo bounds (element ups to gmem; row max-lo) --------
    #pragma unroll
    for (int mi = 0; mi < 4; mi++) {
        int rl = wy * 64 + mi * 16 + (l >> 2);
        float szl = s_sz[rl],     Pl = s_P[rl];
        float szh = s_sz[rl + 8], Ph = s_P[rl + 8];
        float lomax_l = -FLT_MAX, lomax_h = -FLT_MAX;
        #pragma unroll
        for (int ni = 0; ni < 4; ni++) {
            int ncol = wx * 32 + ni * 8 + 2 * (l & 3);
            float se0 = s_se[ncol], Q0 = s_Q[ncol];
            float se1 = s_se[ncol + 1], Q1 = s_Q[ncol + 1];
            float d00 = (float)c[mi][ni][0], d01 = (float)c[mi][ni][1];
            float d10 = (float)c[mi][ni][2], d11 = (float)c[mi][ni][3];
            float k00 = szl * se0, k01 = szl * se1, k10 = szh * se0, k11 = szh * se1;
            float b00 = Pl + Q0, b01 = Pl + Q1, b10 = Ph + Q0, b11 = Ph + Q1;
            float up00 = k00 * (d00 + b00), lo00 = k00 * (d00 - b00);
            float up01 = k01 * (d01 + b01), lo01 = k01 * (d01 - b01);
            float up10 = k10 * (d10 + b10), lo10 = k10 * (d10 - b10);
            float up11 = k11 * (d11 + b11), lo11 = k11 * (d11 - b11);
            __half2* pl = (__half2*)&g_up[(size_t)(m0 + rl) * NCODES + n0 + ncol];
            __half2* ph = (__half2*)&g_up[(size_t)(m0 + rl + 8) * NCODES + n0 + ncol];
            *pl = __halves2half2(__float2half_ru(up00), __float2half_ru(up01));
            *ph = __halves2half2(__float2half_ru(up10), __float2half_ru(up11));
            lomax_l = fmaxf(lomax_l, fmaxf(lo00, lo01));
            lomax_h = fmaxf(lomax_h, fmaxf(lo10, lo11));
        }
        atomicMax(&s_lo[rl], fkey(lomax_l));
        atomicMax(&s_lo[rl + 8], fkey(lomax_h));
    }
    __syncthreads();
    if (tid < 128) atomicMax(&g_maxlo[m0 + tid], s_lo[tid]);
}

// ---------------- Flat scan + exact fp32 rescore (warp per row) ----------------
__global__ __launch_bounds__(256)
void scan_rescore_kernel(const float* __restrict__ emb) {
    int m = blockIdx.x * 8 + (threadIdx.x >> 5);
    int lane = threadIdx.x & 31;
    const unsigned FULL = 0xffffffffu;

    float zr[16];
    const float* zrow = g_zt + (size_t)m * DDIM;
    #pragma unroll
    for (int i = 0; i < 16; i++) zr[i] = zrow[lane + 32 * i];

    float maxlo = unkey(g_maxlo[m]);
    unsigned long long best = 0ULL;

    const uint4* rowp = (const uint4*)(g_up + (size_t)m * NCODES);
    #pragma unroll 1
    for (int it = 0; it < 32; it++) {
        uint4 v = rowp[it * 32 + lane];
        unsigned mym = 0;
        const unsigned vv[4] = {v.x, v.y, v.z, v.w};
        #pragma unroll
        for (int p = 0; p < 4; p++) {
            float2 f = __half22float2(*(const __half2*)&vv[p]);
            if (f.x >= maxlo) mym |= 1u << (2 * p);
            if (f.y >= maxlo) mym |= 1u << (2 * p + 1);
        }
        unsigned act = __ballot_sync(FULL, mym != 0);
        while (act) {
            int src = __ffs(act) - 1;
            act &= act - 1;
            unsigned mm = __shfl_sync(FULL, mym, src);
            int nb = it * 256 + src * 8;
            while (mm) {
                int j = __ffs(mm) - 1;
                mm &= mm - 1;
                int n = nb + j;
                const float* er = emb + (size_t)n * DDIM;
                float s = 0.f;
                #pragma unroll
                for (int i = 0; i < 16; i++) s = fmaf(zr[i], er[lane + 32 * i], s);
                #pragma unroll
                for (int o = 16; o; o >>= 1) s += __shfl_xor_sync(FULL, s, o);
                s *= g_inv_norm[n];
                unsigned long long key = pack_key(s, n);
                if (key > best) best = key;
            }
        }
    }
    if (lane == 0) g_best[m] = best;
}

// ---------------- Gather + outputs ----------------
__global__ __launch_bounds__(256)
void gather_kernel(const float* __restrict__ z, const float* __restrict__ emb,
                   float* __restrict__ out) {
    __shared__ float tile[32][33];
    __shared__ int sidx[32];

    const int r0 = blockIdx.x * 32;
    const int tid = threadIdx.x;
    const int tx = tid & 31;
    const int tyw = tid >> 5;

    if (tid < 32) {
        unsigned long long p = g_best[r0 + tid];
        int n = (int)(0xFFFFFFFFu - (unsigned)(p & 0xFFFFFFFFu));
        sidx[tid] = n;
        out[(size_t)BATCH * DDIM * TQ + r0 + tid] = (float)n;
    }
    __syncthreads();

    const int b = r0 / TQ;
    const int t0 = r0 % TQ;
    float* out_st = out;
    float* out_q  = out + (size_t)BATCH * DDIM * TQ + MROWS;

    for (int cc = 0; cc < DDIM; cc += 32) {
        #pragma unroll
        for (int i = 0; i < 4; i++) {
            int row = tyw + i * 8;
            tile[row][tx] = emb[(size_t)sidx[row] * DDIM + cc + tx];
        }
        __syncthreads();
        #pragma unroll
        for (int i = 0; i < 4; i++) {
            int cidx = cc + tyw + i * 8;
            size_t o = ((size_t)b * DDIM + cidx) * TQ + t0 + tx;
            float v = tile[tx][tyw + i * 8];
            out_q[o] = v;
            float zz = z[o];
            out_st[o] = zz + (v - zz);
        }
        __syncthreads();
    }
}

// ---------------- Launch ----------------
extern "C" void kernel_launch(void* const* d_in, const int* in_sizes, int n_in,
                              void* d_out, int out_size) {
    const float* z   = (const float*)d_in[0];   // [4, 512, 4096]
    const float* emb = (const float*)d_in[1];   // [8192, 512]
    float* out = (float*)d_out;

    float* d_zt;
    cudaGetSymbolAddress((void**)&d_zt, g_zt);
    unsigned *d_zq, *d_eq;
    cudaGetSymbolAddress((void**)&d_zq, g_zq);
    cudaGetSymbolAddress((void**)&d_eq, g_eq);
    float *d_sz, *d_P, *d_se, *d_Q, *d_inv;
    cudaGetSymbolAddress((void**)&d_sz, g_sz);
    cudaGetSymbolAddress((void**)&d_P, g_P);
    cudaGetSymbolAddress((void**)&d_se, g_se);
    cudaGetSymbolAddress((void**)&d_Q, g_Q);
    cudaGetSymbolAddress((void**)&d_inv, g_inv_norm);

    inv_norm_kernel<<<NCODES / 8, 256>>>(emb);   // also zeroes g_maxlo
    quant_kernel<128><<<NCODES / 8, 256>>>(emb, d_eq, d_se, d_Q, d_inv);
    transpose_z_kernel<<<dim3(TQ / 32, DDIM / 32, BATCH), 256>>>(z);
    quant_kernel<128><<<MROWS / 8, 256>>>(d_zt, d_zq, d_sz, d_P, nullptr);

    gemm_bound_kernel<<<NBLK * MBLK, 256>>>();

    scan_rescore_kernel<<<MROWS / 8, 256>>>(emb);
    gather_kernel<<<MROWS / 32, 256>>>(z, emb, out);
}

// round 11
// speedup vs baseline: 4.5682x; 1.0304x over previous
#include <cuda_runtime.h>
#include <cuda_fp16.h>
#include <stdint.h>
#include <float.h>

// ---------------- Problem constants ----------------
#define BATCH   4
#define DDIM    512
#define TQ      4096
#define MROWS   (BATCH * TQ)      // 16384
#define NCODES  8192

// ---------------- GEMM tiling (int8) ----------------
#define BM 128
#define BN 128
#define BK 64                     // int8 elems per stage = 64 bytes/row
#define NBLK   (NCODES / BN)      // 64
#define MBLK   (MROWS / BM)       // 128
#define NSTAGE (DDIM / BK)        // 8

#define ROWPITCH 80               // 64B data + 16B pad
#define AMAT  (128 * ROWPITCH)    // 10240
#define B_OFF AMAT
#define STAGE (2 * AMAT)          // 20480
#define SMEM_GEMM (2 * STAGE)     // 40960 (static)

// ---------------- Device scratch ----------------
__device__ float g_zt[(size_t)MROWS * DDIM];          // transposed z (fp32), 64MB
__device__ unsigned g_zq[(size_t)MROWS * DDIM / 4];   // int8 quantized z, 8MB
__device__ unsigned g_eq[(size_t)NCODES * DDIM / 4];  // int8 quantized e', 4MB
__device__ float g_sz[MROWS], g_P[MROWS];             // z scales + bound terms
__device__ float g_se[NCODES], g_Q[NCODES];           // e scales + bound terms
__device__ float g_inv_norm[NCODES];
__device__ __half g_up[(size_t)MROWS * NCODES];       // upper bounds, 256MB
__device__ unsigned g_maxlo[MROWS];                   // fkey(max lower bound)
__device__ unsigned long long g_best[MROWS];

// ---------------- helpers ----------------
__device__ __forceinline__ uint32_t smem_u32(const void* p) {
    uint32_t a;
    asm("{ .reg .u64 t; cvta.to.shared.u64 t, %1; cvt.u32.u64 %0, t; }" : "=r"(a) : "l"(p));
    return a;
}
__device__ __forceinline__ void cpasync16(uint32_t dst, const void* src) {
    asm volatile("cp.async.cg.shared.global [%0], [%1], 16;" :: "r"(dst), "l"(src) : "memory");
}
#define CP_COMMIT() asm volatile("cp.async.commit_group;" ::: "memory")
#define CP_WAIT(n)  asm volatile("cp.async.wait_group %0;" :: "n"(n) : "memory")

#define LDSM4(R, addr) \
    asm volatile("ldmatrix.sync.aligned.m8n8.x4.shared.b16 {%0,%1,%2,%3}, [%4];" \
                 : "=r"((R)[0]), "=r"((R)[1]), "=r"((R)[2]), "=r"((R)[3]) : "r"(addr))

#define MMA_S8(C, A, b0v, b1v) \
    asm volatile("mma.sync.aligned.m16n8k32.row.col.s32.s8.s8.s32 " \
                 "{%0,%1,%2,%3}, {%4,%5,%6,%7}, {%8,%9}, {%0,%1,%2,%3};" \
                 : "+r"((C)[0]), "+r"((C)[1]), "+r"((C)[2]), "+r"((C)[3]) \
                 : "r"((A)[0]), "r"((A)[1]), "r"((A)[2]), "r"((A)[3]), "r"(b0v), "r"(b1v))

__device__ __forceinline__ unsigned int fkey(float v) {
    unsigned int u = __float_as_uint(v);
    return (u & 0x80000000u) ? ~u : (u | 0x80000000u);
}
__device__ __forceinline__ float unkey(unsigned int k) {
    unsigned int u = (k & 0x80000000u) ? (k ^ 0x80000000u) : ~k;
    return __uint_as_float(u);
}
__device__ __forceinline__ unsigned long long pack_key(float v, int n) {
    return ((unsigned long long)fkey(v) << 32) | (unsigned long long)(0xFFFFFFFFu - (unsigned)n);
}

// ---------------- Small kernels ----------------
// inv_norm + g_maxlo init fused
__global__ void inv_norm_kernel(const float* __restrict__ emb) {
    int gidx = blockIdx.x * blockDim.x + threadIdx.x;
    if (gidx < MROWS) g_maxlo[gidx] = 0u;
    int warp = gidx >> 5;
    int lane = threadIdx.x & 31;
    if (warp >= NCODES) return;
    const float* row = emb + (size_t)warp * DDIM;
    float s = 0.f;
    #pragma unroll
    for (int k = lane; k < DDIM; k += 32) { float v = row[k]; s = fmaf(v, v, s); }
    #pragma unroll
    for (int o = 16; o; o >>= 1) s += __shfl_down_sync(0xffffffffu, s, o);
    if (lane == 0) g_inv_norm[warp] = 1.0f / fmaxf(sqrtf(s), 1e-12f);
}

// Transpose z: [b][k][t] -> z_t[m=b*TQ+t][k] fp32
__global__ __launch_bounds__(256) void transpose_z_kernel(const float* __restrict__ z) {
    __shared__ float tile[32][33];
    int b  = blockIdx.z;
    int k0 = blockIdx.y * 32;
    int t0 = blockIdx.x * 32;
    int tx = threadIdx.x & 31, ty = threadIdx.x >> 5;
    #pragma unroll
    for (int i = 0; i < 4; i++) {
        int kl = ty + i * 8;
        tile[kl][tx] = z[((size_t)b * DDIM + k0 + kl) * TQ + t0 + tx];
    }
    __syncthreads();
    #pragma unroll
    for (int i = 0; i < 4; i++) {
        int tl = ty + i * 8;
        int m = b * TQ + t0 + tl;
        g_zt[(size_t)m * DDIM + k0 + tx] = tile[tx][tl];
    }
}

// Generic per-row int8 quantizer: warp per row of 512 floats.
template <int ADDC>
__global__ __launch_bounds__(256) void quant_kernel(const float* __restrict__ src,
                                                    unsigned* __restrict__ qdst,
                                                    float* __restrict__ scale,
                                                    float* __restrict__ bterm,
                                                    const float* __restrict__ rowscale) {
    int row = blockIdx.x * 8 + (threadIdx.x >> 5);
    int lane = threadIdx.x & 31;
    float rs = rowscale ? rowscale[row] : 1.0f;
    float v[16];
    const float4* sp = (const float4*)(src + (size_t)row * DDIM + lane * 16);
    #pragma unroll
    for (int j = 0; j < 4; j++) {
        float4 f = sp[j];
        v[j*4+0] = f.x * rs; v[j*4+1] = f.y * rs; v[j*4+2] = f.z * rs; v[j*4+3] = f.w * rs;
    }
    float amax = 0.f;
    #pragma unroll
    for (int j = 0; j < 16; j++) amax = fmaxf(amax, fabsf(v[j]));
    #pragma unroll
    for (int o = 16; o; o >>= 1) amax = fmaxf(amax, __shfl_xor_sync(0xffffffffu, amax, o));
    amax = fmaxf(amax, 1e-30f);
    float sc = amax / 127.0f;
    float inv = 127.0f / amax;
    int q[16], sabs = 0;
    #pragma unroll
    for (int j = 0; j < 16; j++) {
        int qq = __float2int_rn(v[j] * inv);
        qq = max(-127, min(127, qq));
        q[j] = qq;
        sabs += abs(qq);
    }
    #pragma unroll
    for (int o = 16; o; o >>= 1) sabs += __shfl_xor_sync(0xffffffffu, sabs, o);
    unsigned w[4];
    #pragma unroll
    for (int g = 0; g < 4; g++)
        w[g] = (unsigned)(q[g*4] & 0xFF) | ((unsigned)(q[g*4+1] & 0xFF) << 8) |
               ((unsigned)(q[g*4+2] & 0xFF) << 16) | ((unsigned)(q[g*4+3] & 0xFF) << 24);
    uint4* dp = (uint4*)(qdst + (size_t)row * (DDIM / 4) + lane * 4);
    *dp = make_uint4(w[0], w[1], w[2], w[3]);
    if (lane == 0) {
        scale[row] = sc;
        bterm[row] = 0.5f * (float)sabs + (float)ADDC;
    }
}

// ---------------- int8 GEMM + bound epilogue ----------------
__device__ __forceinline__ void load_stage(uint32_t sbase, int tid, int m0, int n0, int k0) {
    #pragma unroll
    for (int it = 0; it < 2; it++) {
        int c = it * 256 + tid;
        int row = c >> 2, col = c & 3;
        cpasync16(sbase + (uint32_t)(row * ROWPITCH + col * 16),
                  (const char*)g_zq + (size_t)(m0 + row) * DDIM + k0 + col * 16);
    }
    #pragma unroll
    for (int it = 0; it < 2; it++) {
        int c = it * 256 + tid;
        int row = c >> 2, col = c & 3;
        cpasync16(sbase + B_OFF + (uint32_t)(row * ROWPITCH + col * 16),
                  (const char*)g_eq + (size_t)(n0 + row) * DDIM + k0 + col * 16);
    }
}

__global__ __launch_bounds__(256, 2)
void gemm_bound_kernel() {
    __shared__ char smem[SMEM_GEMM];
    __shared__ float s_sz[128], s_P[128], s_se[128], s_Q[128];
    __shared__ unsigned s_lo[128];
    uint32_t sb = smem_u32(smem);
    const int tid = threadIdx.x;
    const int w = tid >> 5, l = tid & 31;
    const int wy = w >> 2, wx = w & 3;

    const int bid  = blockIdx.x;
    const int band = bid >> 10;
    const int rem  = bid & 1023;
    const int m0 = ((band << 4) | (rem & 15)) * BM;
    const int n0 = (rem >> 4) * BN;

    if (tid < 128) {
        s_sz[tid] = g_sz[m0 + tid];
        s_P[tid]  = g_P[m0 + tid];
        s_se[tid] = g_se[n0 + tid];
        s_Q[tid]  = g_Q[n0 + tid];
        s_lo[tid] = 0u;
    }

    int c[4][4][4];
    #pragma unroll
    for (int i = 0; i < 4; i++)
        #pragma unroll
        for (int j = 0; j < 4; j++)
            #pragma unroll
            for (int r = 0; r < 4; r++) c[i][j][r] = 0;

    const uint32_t aBase = sb + (uint32_t)((wy * 64 + (l & 15)) * ROWPITCH + ((l >> 4) << 4));
    const uint32_t bBase = sb + B_OFF +
        (uint32_t)((wx * 32 + ((l >> 4) & 1) * 8 + (l & 7)) * ROWPITCH + ((l >> 3) & 1) * 16);

    load_stage(sb, tid, m0, n0, 0);
    CP_COMMIT();

    #pragma unroll 1
    for (int s = 0; s < NSTAGE; s++) {
        if (s > 0) __syncthreads();
        if (s + 1 < NSTAGE) {
            load_stage(sb + ((s + 1) & 1) * STAGE, tid, m0, n0, (s + 1) * BK);
            CP_COMMIT();
            CP_WAIT(1);
        } else {
            CP_WAIT(0);
        }
        __syncthreads();

        const uint32_t so = (uint32_t)((s & 1) * STAGE);
        #pragma unroll
        for (int ks = 0; ks < 2; ks++) {
            uint32_t ah[4][4];
            #pragma unroll
            for (int mi = 0; mi < 4; mi++)
                LDSM4(ah[mi], aBase + so + (uint32_t)(mi * 16 * ROWPITCH + ks * 32));
            uint32_t bh[2][4];
            #pragma unroll
            for (int np = 0; np < 2; np++)
                LDSM4(bh[np], bBase + so + (uint32_t)(np * 16 * ROWPITCH + ks * 32));
            #pragma unroll
            for (int mi = 0; mi < 4; mi++)
                #pragma unroll
                for (int ni = 0; ni < 4; ni++) {
                    int np = ni >> 1, q = (ni & 1) * 2;
                    MMA_S8(c[mi][ni], ah[mi], bh[np][q], bh[np][q + 1]);
                }
        }
    }

    // -------- epilogue: up/lo bounds (element ups to gmem; row max-lo) --------
    #pragma unroll
    for (int mi = 0; mi < 4; mi++) {
        int rl = wy * 64 + mi * 16 + (l >> 2);
        float szl = s_sz[rl],     Pl = s_P[rl];
        float szh = s_sz[rl + 8], Ph = s_P[rl + 8];
        float lomax_l = -FLT_MAX, lomax_h = -FLT_MAX;
        #pragma unroll
        for (int ni = 0; ni < 4; ni++) {
            int ncol = wx * 32 + ni * 8 + 2 * (l & 3);
            float se0 = s_se[ncol], Q0 = s_Q[ncol];
            float se1 = s_se[ncol + 1], Q1 = s_Q[ncol + 1];
            float d00 = (float)c[mi][ni][0], d01 = (float)c[mi][ni][1];
            float d10 = (float)c[mi][ni][2], d11 = (float)c[mi][ni][3];
            float k00 = szl * se0, k01 = szl * se1, k10 = szh * se0, k11 = szh * se1;
            float b00 = Pl + Q0, b01 = Pl + Q1, b10 = Ph + Q0, b11 = Ph + Q1;
            float up00 = k00 * (d00 + b00), lo00 = k00 * (d00 - b00);
            float up01 = k01 * (d01 + b01), lo01 = k01 * (d01 - b01);
            float up10 = k10 * (d10 + b10), lo10 = k10 * (d10 - b10);
            float up11 = k11 * (d11 + b11), lo11 = k11 * (d11 - b11);
            __half2* pl = (__half2*)&g_up[(size_t)(m0 + rl) * NCODES + n0 + ncol];
            __half2* ph = (__half2*)&g_up[(size_t)(m0 + rl + 8) * NCODES + n0 + ncol];
            *pl = __halves2half2(__float2half_ru(up00), __float2half_ru(up01));
            *ph = __halves2half2(__float2half_ru(up10), __float2half_ru(up11));
            lomax_l = fmaxf(lomax_l, fmaxf(lo00, lo01));
            lomax_h = fmaxf(lomax_h, fmaxf(lo10, lo11));
        }
        atomicMax(&s_lo[rl], fkey(lomax_l));
        atomicMax(&s_lo[rl + 8], fkey(lomax_h));
    }
    __syncthreads();
    if (tid < 128) atomicMax(&g_maxlo[m0 + tid], s_lo[tid]);
}

// ---------------- Flat scan + exact fp32 rescore (warp per row, MLP=4) ----------------
__global__ __launch_bounds__(256)
void scan_rescore_kernel(const float* __restrict__ emb) {
    int m = blockIdx.x * 8 + (threadIdx.x >> 5);
    int lane = threadIdx.x & 31;
    const unsigned FULL = 0xffffffffu;

    float zr[16];
    const float* zrow = g_zt + (size_t)m * DDIM;
    #pragma unroll
    for (int i = 0; i < 16; i++) zr[i] = zrow[lane + 32 * i];

    float maxlo = unkey(g_maxlo[m]);
    unsigned long long best = 0ULL;

    const uint4* rowp = (const uint4*)(g_up + (size_t)m * NCODES);
    #pragma unroll 1
    for (int it = 0; it < 32; it += 4) {
        // batch 4 independent 16B loads -> MLP=4 (overlaps DRAM latency)
        uint4 vbuf[4];
        #pragma unroll
        for (int u = 0; u < 4; u++)
            vbuf[u] = rowp[(it + u) * 32 + lane];

        #pragma unroll
        for (int u = 0; u < 4; u++) {
            unsigned mym = 0;
            const unsigned vv[4] = {vbuf[u].x, vbuf[u].y, vbuf[u].z, vbuf[u].w};
            #pragma unroll
            for (int p = 0; p < 4; p++) {
                float2 f = __half22float2(*(const __half2*)&vv[p]);
                if (f.x >= maxlo) mym |= 1u << (2 * p);
                if (f.y >= maxlo) mym |= 1u << (2 * p + 1);
            }
            unsigned act = __ballot_sync(FULL, mym != 0);
            while (act) {
                int src = __ffs(act) - 1;
                act &= act - 1;
                unsigned mm = __shfl_sync(FULL, mym, src);
                int nb = (it + u) * 256 + src * 8;
                while (mm) {
                    int j = __ffs(mm) - 1;
                    mm &= mm - 1;
                    int n = nb + j;
                    const float* er = emb + (size_t)n * DDIM;
                    float s = 0.f;
                    #pragma unroll
                    for (int i = 0; i < 16; i++) s = fmaf(zr[i], er[lane + 32 * i], s);
                    #pragma unroll
                    for (int o = 16; o; o >>= 1) s += __shfl_xor_sync(FULL, s, o);
                    s *= g_inv_norm[n];
                    unsigned long long key = pack_key(s, n);
                    if (key > best) best = key;
                }
            }
        }
    }
    if (lane == 0) g_best[m] = best;
}

// ---------------- Gather + outputs ----------------
__global__ __launch_bounds__(256)
void gather_kernel(const float* __restrict__ z, const float* __restrict__ emb,
                   float* __restrict__ out) {
    __shared__ float tile[32][33];
    __shared__ int sidx[32];

    const int r0 = blockIdx.x * 32;
    const int tid = threadIdx.x;
    const int tx = tid & 31;
    const int tyw = tid >> 5;

    if (tid < 32) {
        unsigned long long p = g_best[r0 + tid];
        int n = (int)(0xFFFFFFFFu - (unsigned)(p & 0xFFFFFFFFu));
        sidx[tid] = n;
        out[(size_t)BATCH * DDIM * TQ + r0 + tid] = (float)n;
    }
    __syncthreads();

    const int b = r0 / TQ;
    const int t0 = r0 % TQ;
    float* out_st = out;
    float* out_q  = out + (size_t)BATCH * DDIM * TQ + MROWS;

    for (int cc = 0; cc < DDIM; cc += 32) {
        #pragma unroll
        for (int i = 0; i < 4; i++) {
            int row = tyw + i * 8;
            tile[row][tx] = emb[(size_t)sidx[row] * DDIM + cc + tx];
        }
        __syncthreads();
        #pragma unroll
        for (int i = 0; i < 4; i++) {
            int cidx = cc + tyw + i * 8;
            size_t o = ((size_t)b * DDIM + cidx) * TQ + t0 + tx;
            float v = tile[tx][tyw + i * 8];
            out_q[o] = v;
            float zz = z[o];
            out_st[o] = zz + (v - zz);
        }
        __syncthreads();
    }
}

// ---------------- Launch ----------------
extern "C" void kernel_launch(void* const* d_in, const int* in_sizes, int n_in,
                              void* d_out, int out_size) {
    const float* z   = (const float*)d_in[0];   // [4, 512, 4096]
    const float* emb = (const float*)d_in[1];   // [8192, 512]
    float* out = (float*)d_out;

    float* d_zt;
    cudaGetSymbolAddress((void**)&d_zt, g_zt);
    unsigned *d_zq, *d_eq;
    cudaGetSymbolAddress((void**)&d_zq, g_zq);
    cudaGetSymbolAddress((void**)&d_eq, g_eq);
    float *d_sz, *d_P, *d_se, *d_Q, *d_inv;
    cudaGetSymbolAddress((void**)&d_sz, g_sz);
    cudaGetSymbolAddress((void**)&d_P, g_P);
    cudaGetSymbolAddress((void**)&d_se, g_se);
    cudaGetSymbolAddress((void**)&d_Q, g_Q);
    cudaGetSymbolAddress((void**)&d_inv, g_inv_norm);

    inv_norm_kernel<<<NCODES / 8, 256>>>(emb);   // also zeroes g_maxlo
    quant_kernel<128><<<NCODES / 8, 256>>>(emb, d_eq, d_se, d_Q, d_inv);
    transpose_z_kernel<<<dim3(TQ / 32, DDIM / 32, BATCH), 256>>>(z);
    quant_kernel<128><<<MROWS / 8, 256>>>(d_zt, d_zq, d_sz, d_P, nullptr);

    gemm_bound_kernel<<<NBLK * MBLK, 256>>>();

    scan_rescore_kernel<<<MROWS / 8, 256>>>(emb);
    gather_kernel<<<MROWS / 32, 256>>>(z, emb, out);
}